// round 4
// baseline (speedup 1.0000x reference)
#include <cuda_runtime.h>
#include <cstdint>

#define NSPEC 1024
#define NR1   2048
#define NR2   8192
#define NRTOT (NR1 + NR2)
#define NB    32                   // batches per CTA (lane = batch)
#define WARPS 20
#define THREADS (WARPS * 32)
#define NCHUNK 32                  // 32 product-chunks of 32 products
#define YP    33                   // padded row stride (floats)
#define YPB   (YP * 4)             // row stride bytes (132)
#define ONES_ROW NSPEC
#define NSETUP 16                  // CTAs participating in scatter

// ---------------- device scratch ----------------
__device__ int  g_off[NSPEC + 1];
__device__ int  g_cur[NSPEC];      // monotonic across replays (mod-cnt trick)
__device__ int4 g_e[NRTOT];        // .x/.y = byte offs into y_s rows, .z = k bits,
                                   // .w = dst byte off | 1 on last entry of product
__device__ int  g_flag1;           // off[] ready
__device__ int  g_ready;           // scatter done counter (target NSETUP)
__device__ int  g_done;            // CTA completion counter

// ---------------- smem layout (bytes) ----------------
#define YS_B     ((NSPEC + 1) * YP * 4)            // 135300
#define TS_B     (NB * 4)                          // 128
#define OTILE_B  (WARPS * 32 * YP * 4)             // 84480
#define SMEM_BYTES (YS_B + TS_B + OTILE_B)         // 219908 < 227KB

extern "C" __global__ void __launch_bounds__(THREADS, 1)
reaction_fused_kernel(const float* __restrict__ t_in,
                      const float* __restrict__ y_in,
                      const float* __restrict__ k1,
                      const float* __restrict__ k2,
                      const int*   __restrict__ i1r,
                      const int*   __restrict__ i1p,
                      const int*   __restrict__ i2r,
                      const int*   __restrict__ i2p,
                      float* __restrict__ y_out,
                      int grid_size) {
    extern __shared__ char smem[];
    float* y_s    = (float*)smem;
    float* t_s    = (float*)(smem + YS_B);
    char*  otile0 = smem + YS_B + TS_B;

    const int tid  = threadIdx.x;
    const int lane = tid & 31;
    const int warp = tid >> 5;
    const int cta  = blockIdx.x;
    const int b0   = cta * NB;

    __shared__ int s_chunk;
    if (tid == 0) s_chunk = 0;

    // ============ setup: CTA0 hist+scan; CTAs 0..15 scatter 1/16 each ======
    if (cta == 0) {
        int* s_cnt  = (int*)otile0;            // 1024 ints scratch (pre-hotloop)
        int* s_wsum = s_cnt + NSPEC;           // 16
        for (int i = tid; i < NSPEC; i += THREADS) s_cnt[i] = 0;
        __syncthreads();
        for (int i = tid; i < NR1; i += THREADS) atomicAdd(&s_cnt[i1p[i]], 1);
        for (int i = tid; i < NR2; i += THREADS) atomicAdd(&s_cnt[i2p[i]], 1);
        __syncthreads();
        if (tid < 512) {                       // 16 warps scan 2 bins/thread
            const int a = s_cnt[2 * tid];
            const int b = s_cnt[2 * tid + 1];
            int incl = a + b;
#pragma unroll
            for (int d = 1; d < 32; d <<= 1) {
                int n = __shfl_up_sync(0xFFFFFFFFu, incl, d);
                if (lane >= d) incl += n;
            }
            if (lane == 31) s_wsum[warp] = incl;
            __syncthreads();
            if (warp == 0) {
                int w = (lane < 16) ? s_wsum[lane] : 0;
#pragma unroll
                for (int d = 1; d < 32; d <<= 1) {
                    int n = __shfl_up_sync(0xFFFFFFFFu, w, d);
                    if (lane >= d) w += n;
                }
                if (lane < 16) s_wsum[lane] = w;
            }
            __syncthreads();
            if (warp > 0) incl += s_wsum[warp - 1];
            const int e0 = incl - a - b;
            g_off[2 * tid]     = e0;
            g_off[2 * tid + 1] = e0 + a;
            if (tid == 511) g_off[NSPEC] = incl;
        } else {
            __syncthreads(); __syncthreads();
        }
        __threadfence();
        __syncthreads();
        if (tid == 0) atomicExch(&g_flag1, 1);
    }

    if (cta < NSETUP) {
        if (cta != 0) {
            if (tid == 0) {
                while (atomicAdd(&g_flag1, 0) == 0) __nanosleep(128);
            }
            __syncthreads();
        }
        const int per1 = NR1 / NSETUP, per2 = NR2 / NSETUP;
        for (int r = cta * per1 + tid; r < (cta + 1) * per1; r += THREADS) {
            const int p    = i1p[r];
            const int o0   = g_off[p], o1 = g_off[p + 1];
            const int cnt  = o1 - o0;
            const int posP = atomicAdd(&g_cur[p], 1) % cnt;   // epoch-free
            const int last = (posP == cnt - 1) ? 1 : 0;
            g_e[o0 + posP] = make_int4(i1r[r] * YPB, ONES_ROW * YPB,
                                       __float_as_int(k1[r]),
                                       ((p & 31) * YPB) | last);
        }
        for (int r = cta * per2 + tid; r < (cta + 1) * per2; r += THREADS) {
            const int p    = i2p[r];
            const int o0   = g_off[p], o1 = g_off[p + 1];
            const int cnt  = o1 - o0;
            const int posP = atomicAdd(&g_cur[p], 1) % cnt;
            const int last = (posP == cnt - 1) ? 1 : 0;
            g_e[o0 + posP] = make_int4(i2r[2 * r] * YPB, i2r[2 * r + 1] * YPB,
                                       __float_as_int(k2[r]),
                                       ((p & 31) * YPB) | last);
        }
        __threadfence();
        __syncthreads();
        if (tid == 0) atomicAdd(&g_ready, 1);
    }

    // ============ all CTAs: load y tile transposed into smem ================
    if (tid < NB) t_s[tid] = t_in[b0 + tid];
    if (tid < NB) y_s[ONES_ROW * YP + tid] = 1.0f;
    {
        const float4* y4 = (const float4*)(y_in + (size_t)b0 * NSPEC);
        for (int i = tid; i < NB * NSPEC / 4; i += THREADS) {
            const float4 v = y4[i];
            const int b = i >> 8;
            const int s = (i & 255) * 4;
            y_s[(s + 0) * YP + b] = v.x;
            y_s[(s + 1) * YP + b] = v.y;
            y_s[(s + 2) * YP + b] = v.z;
            y_s[(s + 3) * YP + b] = v.w;
        }
    }

    if (tid == 0) {
        while (atomicAdd(&g_ready, 0) < NSETUP) __nanosleep(128);
    }
    __syncthreads();

    // ============ hot loop: pair-processed entries, warp-uniform LDG ========
    const char* ysl = (const char*)y_s + lane * 4;     // lane-baked base
    char*       otl = otile0 + (warp * 32 * YP + lane) * 4;

    for (;;) {
        int c;
        if (lane == 0) c = atomicAdd(&s_chunk, 1);
        c = __shfl_sync(0xFFFFFFFFu, c, 0);
        if (c >= NCHUNK) break;
        const int pc = c * 32;
        const int j0 = g_off[pc];
        const int j1 = g_off[pc + 32];

#pragma unroll
        for (int pp = 0; pp < 32; ++pp)
            *(float*)(otl + pp * YPB) = 0.0f;

        float acc = 0.0f;
        int j = j0;
        const int npairs = (j1 - j0) >> 1;

#pragma unroll 2
        for (int it = 0; it < npairs; ++it, j += 2) {
            const int4 e0 = g_e[j];
            const int4 e1 = g_e[j + 1];
            const float q0 = *(const float*)(ysl + e0.x) * *(const float*)(ysl + e0.y);
            const float q1 = *(const float*)(ysl + e1.x) * *(const float*)(ysl + e1.y);
            if (((e0.w | e1.w) & 1) == 0) {
                // fast path: no flush in this pair (chain = 1 FADD / pair)
                acc = acc + fmaf(__int_as_float(e1.z), q1,
                                 __int_as_float(e0.z) * q0);
            } else {
                const float v0 = fmaf(__int_as_float(e0.z), q0, acc);
                float v1;
                if (e0.w & 1) {
                    *(float*)(otl + (e0.w & ~3)) = v0;
                    v1 = __int_as_float(e1.z) * q1;
                } else {
                    v1 = fmaf(__int_as_float(e1.z), q1, v0);
                }
                if (e1.w & 1) {
                    *(float*)(otl + (e1.w & ~3)) = v1;
                    acc = 0.0f;
                } else {
                    acc = v1;
                }
            }
        }
        if (j < j1) {                          // odd tail (always flushes:
            const int4 e0 = g_e[j];            //  last entry of chunk has flag)
            const float q0 = *(const float*)(ysl + e0.x) * *(const float*)(ysl + e0.y);
            const float v0 = fmaf(__int_as_float(e0.z), q0, acc);
            if (e0.w & 1) *(float*)(otl + (e0.w & ~3)) = v0;
            acc = 0.0f;
        }
        __syncwarp();   // otile visibility across lanes for transposed read

        const float* ot_rd = (const float*)(otile0 + (warp * 32 * YP + lane * YP) * 4);
#pragma unroll
        for (int row = 0; row < 32; ++row) {
            y_out[(size_t)(b0 + row) * NSPEC + pc + lane] = ot_rd[row] * t_s[row];
        }
        __syncwarp();
    }

    // ============ reset flags for next replay ===============================
    __syncthreads();
    if (tid == 0) {
        const int d = atomicAdd(&g_done, 1);
        if (d == grid_size - 1) {
            atomicExch(&g_ready, 0);
            atomicExch(&g_flag1, 0);
            atomicExch(&g_done, 0);
            // g_cur intentionally NOT reset (mod-cnt epoch trick)
        }
    }
}

// ---------------- launch -----------------------------------------------------
extern "C" void kernel_launch(void* const* d_in, const int* in_sizes, int n_in,
                              void* d_out, int out_size) {
    const float* t_in = (const float*)d_in[0];
    const float* y_in = (const float*)d_in[1];
    const float* k1   = (const float*)d_in[2];
    const float* k2   = (const float*)d_in[3];
    const int*   i1r  = (const int*)d_in[4];
    const int*   i1p  = (const int*)d_in[5];
    const int*   i2r  = (const int*)d_in[6];
    const int*   i2p  = (const int*)d_in[7];
    float* y_out = (float*)d_out;

    const int B    = in_sizes[0];
    const int grid = B / NB;   // 128

    cudaFuncSetAttribute(reaction_fused_kernel,
                         cudaFuncAttributeMaxDynamicSharedMemorySize, SMEM_BYTES);
    reaction_fused_kernel<<<grid, THREADS, SMEM_BYTES>>>(
        t_in, y_in, k1, k2, i1r, i1p, i2r, i2p, y_out, grid);
}

// round 5
// speedup vs baseline: 1.4304x; 1.4304x over previous
#include <cuda_runtime.h>
#include <cstdint>

#define NSPEC 1024
#define NR1   2048
#define NR2   8192
#define NRTOT (NR1 + NR2)
#define NB    32                   // batches per CTA (lane = batch)
#define WARPS 20
#define THREADS (WARPS * 32)
#define NCHUNK 32                  // 32 product-chunks of 32 products
#define YP    33                   // padded row stride (floats)
#define YPB   (YP * 4)             // row stride bytes (132)
#define ONES_ROW NSPEC
#define NSETUP 16                  // CTAs participating in scatter

// ---------------- device scratch ----------------
__device__ int  g_off[NSPEC + 1];
__device__ int  g_cur[NSPEC];      // monotonic across replays (mod-cnt trick)
__device__ int4 g_e[NRTOT];        // .x/.y = byte offs into y_s rows, .z = k bits,
                                   // .w = dst byte off | 1 on last entry of product
__device__ int  g_flag1;           // off[] ready
__device__ int  g_ready;           // scatter done counter (target NSETUP)
__device__ int  g_done;            // CTA completion counter

// ---------------- smem layout (bytes) ----------------
#define SBUF_B   (WARPS * 32 * 16)                 // 10240 entry staging
#define YS_B     ((NSPEC + 1) * YP * 4)            // 135300
#define TS_B     (NB * 4)                          // 128
#define OTILE_B  (WARPS * 32 * YP * 4)             // 84480
#define SMEM_BYTES (SBUF_B + YS_B + TS_B + OTILE_B)  // 230148

extern "C" __global__ void __launch_bounds__(THREADS, 1)
reaction_fused_kernel(const float* __restrict__ t_in,
                      const float* __restrict__ y_in,
                      const float* __restrict__ k1,
                      const float* __restrict__ k2,
                      const int*   __restrict__ i1r,
                      const int*   __restrict__ i1p,
                      const int*   __restrict__ i2r,
                      const int*   __restrict__ i2p,
                      float* __restrict__ y_out,
                      int grid_size) {
    extern __shared__ char smem[];
    int4*  sbuf_all = (int4*)smem;
    float* y_s      = (float*)(smem + SBUF_B);
    float* t_s      = (float*)(smem + SBUF_B + YS_B);
    char*  otile0   = smem + SBUF_B + YS_B + TS_B;

    const int tid  = threadIdx.x;
    const int lane = tid & 31;
    const int warp = tid >> 5;
    const int cta  = blockIdx.x;
    const int b0   = cta * NB;

    __shared__ int s_chunk;
    if (tid == 0) s_chunk = 0;

    // ============ setup: CTA0 hist+scan; CTAs 0..15 scatter 1/16 each ======
    if (cta == 0) {
        int* s_cnt  = (int*)otile0;            // 1024 ints scratch (pre-hotloop)
        int* s_wsum = s_cnt + NSPEC;           // 16
        for (int i = tid; i < NSPEC; i += THREADS) s_cnt[i] = 0;
        __syncthreads();
        for (int i = tid; i < NR1; i += THREADS) atomicAdd(&s_cnt[i1p[i]], 1);
        for (int i = tid; i < NR2; i += THREADS) atomicAdd(&s_cnt[i2p[i]], 1);
        __syncthreads();
        if (tid < 512) {                       // 16 warps scan 2 bins/thread
            const int a = s_cnt[2 * tid];
            const int b = s_cnt[2 * tid + 1];
            int incl = a + b;
#pragma unroll
            for (int d = 1; d < 32; d <<= 1) {
                int n = __shfl_up_sync(0xFFFFFFFFu, incl, d);
                if (lane >= d) incl += n;
            }
            if (lane == 31) s_wsum[warp] = incl;
            __syncthreads();
            if (warp == 0) {
                int w = (lane < 16) ? s_wsum[lane] : 0;
#pragma unroll
                for (int d = 1; d < 32; d <<= 1) {
                    int n = __shfl_up_sync(0xFFFFFFFFu, w, d);
                    if (lane >= d) w += n;
                }
                if (lane < 16) s_wsum[lane] = w;
            }
            __syncthreads();
            if (warp > 0) incl += s_wsum[warp - 1];
            const int e0 = incl - a - b;
            g_off[2 * tid]     = e0;
            g_off[2 * tid + 1] = e0 + a;
            if (tid == 511) g_off[NSPEC] = incl;
        } else {
            __syncthreads(); __syncthreads();
        }
        __threadfence();
        __syncthreads();
        if (tid == 0) atomicExch(&g_flag1, 1);
    }

    if (cta < NSETUP) {
        if (cta != 0) {
            if (tid == 0) {
                while (atomicAdd(&g_flag1, 0) == 0) __nanosleep(128);
            }
            __syncthreads();
        }
        const int per1 = NR1 / NSETUP, per2 = NR2 / NSETUP;
        for (int r = cta * per1 + tid; r < (cta + 1) * per1; r += THREADS) {
            const int p    = i1p[r];
            const int o0   = g_off[p], o1 = g_off[p + 1];
            const int cnt  = o1 - o0;
            const int posP = atomicAdd(&g_cur[p], 1) % cnt;   // epoch-free
            const int last = (posP == cnt - 1) ? 1 : 0;
            g_e[o0 + posP] = make_int4(i1r[r] * YPB, ONES_ROW * YPB,
                                       __float_as_int(k1[r]),
                                       ((p & 31) * YPB) | last);
        }
        for (int r = cta * per2 + tid; r < (cta + 1) * per2; r += THREADS) {
            const int p    = i2p[r];
            const int o0   = g_off[p], o1 = g_off[p + 1];
            const int cnt  = o1 - o0;
            const int posP = atomicAdd(&g_cur[p], 1) % cnt;
            const int last = (posP == cnt - 1) ? 1 : 0;
            g_e[o0 + posP] = make_int4(i2r[2 * r] * YPB, i2r[2 * r + 1] * YPB,
                                       __float_as_int(k2[r]),
                                       ((p & 31) * YPB) | last);
        }
        __threadfence();
        __syncthreads();
        if (tid == 0) atomicAdd(&g_ready, 1);
    }

    // ============ all CTAs: load y tile transposed into smem ================
    if (tid < NB) t_s[tid] = t_in[b0 + tid];
    if (tid < NB) y_s[ONES_ROW * YP + tid] = 1.0f;
    {
        const float4* y4 = (const float4*)(y_in + (size_t)b0 * NSPEC);
        for (int i = tid; i < NB * NSPEC / 4; i += THREADS) {
            const float4 v = y4[i];
            const int b = i >> 8;
            const int s = (i & 255) * 4;
            y_s[(s + 0) * YP + b] = v.x;
            y_s[(s + 1) * YP + b] = v.y;
            y_s[(s + 2) * YP + b] = v.z;
            y_s[(s + 3) * YP + b] = v.w;
        }
    }

    if (tid == 0) {
        while (atomicAdd(&g_ready, 0) < NSETUP) __nanosleep(128);
    }
    __syncthreads();

    // ============ hot loop: staged entries + pair processing ================
    const char* ysl  = (const char*)y_s + lane * 4;    // lane-baked base
    char*       otl  = otile0 + (warp * 32 * YP + lane) * 4;
    int4*       sbuf = sbuf_all + warp * 32;

    for (;;) {
        int c;
        if (lane == 0) c = atomicAdd(&s_chunk, 1);
        c = __shfl_sync(0xFFFFFFFFu, c, 0);
        if (c >= NCHUNK) break;
        const int pc = c * 32;
        const int j0 = g_off[pc];
        const int j1 = g_off[pc + 32];

#pragma unroll
        for (int pp = 0; pp < 32; ++pp)
            *(float*)(otl + pp * YPB) = 0.0f;

        float acc = 0.0f;

        // prefetch first block (coalesced: lane j -> entry j)
        int4 epf;
        if (j0 + lane < j1) epf = g_e[j0 + lane];

        for (int base = j0; base < j1; base += 32) {
            const int n = min(32, j1 - base);
            __syncwarp();
            if (lane < n) sbuf[lane] = epf;
            __syncwarp();
            const int nxt = base + 32;
            if (nxt + lane < j1) epf = g_e[nxt + lane];   // overlap next block

            const int npairs = n >> 1;
#pragma unroll 4
            for (int t = 0; t < npairs; ++t) {
                const int4 e0 = sbuf[2 * t];
                const int4 e1 = sbuf[2 * t + 1];
                const float q0 = *(const float*)(ysl + e0.x) * *(const float*)(ysl + e0.y);
                const float q1 = *(const float*)(ysl + e1.x) * *(const float*)(ysl + e1.y);
                if ((((e0.w | e1.w) & 1) == 0)) {
                    // fast path: no flush in this pair (chain = 1 FADD / pair)
                    acc = acc + fmaf(__int_as_float(e1.z), q1,
                                     __int_as_float(e0.z) * q0);
                } else {
                    const float v0 = fmaf(__int_as_float(e0.z), q0, acc);
                    float v1;
                    if (e0.w & 1) {
                        *(float*)(otl + (e0.w & ~3)) = v0;
                        v1 = __int_as_float(e1.z) * q1;
                    } else {
                        v1 = fmaf(__int_as_float(e1.z), q1, v0);
                    }
                    if (e1.w & 1) {
                        *(float*)(otl + (e1.w & ~3)) = v1;
                        acc = 0.0f;
                    } else {
                        acc = v1;
                    }
                }
            }
            if (n & 1) {                       // odd tail of this block
                const int4 e0 = sbuf[n - 1];
                const float q0 = *(const float*)(ysl + e0.x) * *(const float*)(ysl + e0.y);
                const float v0 = fmaf(__int_as_float(e0.z), q0, acc);
                if (e0.w & 1) {
                    *(float*)(otl + (e0.w & ~3)) = v0;
                    acc = 0.0f;
                } else {
                    acc = v0;
                }
            }
        }
        __syncwarp();   // otile visibility across lanes for transposed read

        const float* ot_rd = (const float*)(otile0 + (warp * 32 * YP + lane * YP) * 4);
#pragma unroll
        for (int row = 0; row < 32; ++row) {
            y_out[(size_t)(b0 + row) * NSPEC + pc + lane] = ot_rd[row] * t_s[row];
        }
        __syncwarp();
    }

    // ============ reset flags for next replay ===============================
    __syncthreads();
    if (tid == 0) {
        const int d = atomicAdd(&g_done, 1);
        if (d == grid_size - 1) {
            atomicExch(&g_ready, 0);
            atomicExch(&g_flag1, 0);
            atomicExch(&g_done, 0);
            // g_cur intentionally NOT reset (mod-cnt epoch trick)
        }
    }
}

// ---------------- launch -----------------------------------------------------
extern "C" void kernel_launch(void* const* d_in, const int* in_sizes, int n_in,
                              void* d_out, int out_size) {
    const float* t_in = (const float*)d_in[0];
    const float* y_in = (const float*)d_in[1];
    const float* k1   = (const float*)d_in[2];
    const float* k2   = (const float*)d_in[3];
    const int*   i1r  = (const int*)d_in[4];
    const int*   i1p  = (const int*)d_in[5];
    const int*   i2r  = (const int*)d_in[6];
    const int*   i2p  = (const int*)d_in[7];
    float* y_out = (float*)d_out;

    const int B    = in_sizes[0];
    const int grid = B / NB;   // 128

    cudaFuncSetAttribute(reaction_fused_kernel,
                         cudaFuncAttributeMaxDynamicSharedMemorySize, SMEM_BYTES);
    reaction_fused_kernel<<<grid, THREADS, SMEM_BYTES>>>(
        t_in, y_in, k1, k2, i1r, i1p, i2r, i2p, y_out, grid);
}

// round 6
// speedup vs baseline: 1.4885x; 1.0406x over previous
#include <cuda_runtime.h>
#include <cstdint>

#define NSPEC 1024
#define NR1   2048
#define NR2   8192
#define NRTOT (NR1 + NR2)
#define NB    32                   // batches per CTA (lane = batch)
#define WARPS 20
#define THREADS (WARPS * 32)
#define NCHUNK 32                  // 32 product-chunks of 32 products
#define YP    33                   // padded row stride (floats)
#define YPB   (YP * 4)             // row stride bytes (132)
#define ONES_ROW NSPEC
#define NSETUP 16                  // CTAs participating in scatter

// ---------------- device scratch ----------------
__device__ int  g_off[NSPEC + 1];
__device__ int  g_cur[NSPEC];      // monotonic across replays (mod-cnt trick)
__device__ int4 g_e[NRTOT];        // .x/.y = byte offs into y_s rows, .z = k bits,
                                   // .w = dst byte off | 1 on last entry of product
__device__ int  g_flag1;           // off[] ready
__device__ int  g_ready;           // scatter done counter (target NSETUP)
__device__ int  g_done;            // CTA completion counter

// ---------------- smem layout (bytes) ----------------
#define SBUF_B   (WARPS * 32 * 16)                 // 10240 entry staging
#define YS_B     ((NSPEC + 1) * YP * 4)            // 135300
#define TS_B     (NB * 4)                          // 128
#define OTILE_B  (WARPS * 32 * YP * 4)             // 84480
#define SMEM_BYTES (SBUF_B + YS_B + TS_B + OTILE_B)  // 230148

// one pair of entries from sbuf
#define PAIR_BODY(T)                                                            \
    {                                                                           \
        const int4 e0 = sbuf[2 * (T)];                                          \
        const int4 e1 = sbuf[2 * (T) + 1];                                      \
        const float q0 = *(const float*)(ysl + e0.x) * *(const float*)(ysl + e0.y); \
        const float q1 = *(const float*)(ysl + e1.x) * *(const float*)(ysl + e1.y); \
        if ((((e0.w | e1.w) & 1) == 0)) {                                       \
            acc = acc + fmaf(__int_as_float(e1.z), q1,                          \
                             __int_as_float(e0.z) * q0);                        \
        } else {                                                                \
            const float v0 = fmaf(__int_as_float(e0.z), q0, acc);               \
            float v1;                                                           \
            if (e0.w & 1) {                                                     \
                *(float*)(otl + (e0.w & ~3)) = v0;                              \
                v1 = __int_as_float(e1.z) * q1;                                 \
            } else {                                                            \
                v1 = fmaf(__int_as_float(e1.z), q1, v0);                        \
            }                                                                   \
            if (e1.w & 1) {                                                     \
                *(float*)(otl + (e1.w & ~3)) = v1;                              \
                acc = 0.0f;                                                     \
            } else {                                                            \
                acc = v1;                                                       \
            }                                                                   \
        }                                                                       \
    }

extern "C" __global__ void __launch_bounds__(THREADS, 1)
reaction_fused_kernel(const float* __restrict__ t_in,
                      const float* __restrict__ y_in,
                      const float* __restrict__ k1,
                      const float* __restrict__ k2,
                      const int*   __restrict__ i1r,
                      const int*   __restrict__ i1p,
                      const int*   __restrict__ i2r,
                      const int*   __restrict__ i2p,
                      float* __restrict__ y_out,
                      int grid_size) {
    extern __shared__ char smem[];
    int4*  sbuf_all = (int4*)smem;
    float* y_s      = (float*)(smem + SBUF_B);
    float* t_s      = (float*)(smem + SBUF_B + YS_B);
    char*  otile0   = smem + SBUF_B + YS_B + TS_B;

    const int tid  = threadIdx.x;
    const int lane = tid & 31;
    const int warp = tid >> 5;
    const int cta  = blockIdx.x;
    const int b0   = cta * NB;

    __shared__ int s_chunk;
    if (tid == 0) s_chunk = 0;

    // ============ setup: CTA0 hist+scan; CTAs 0..15 scatter 1/16 each ======
    if (cta == 0) {
        int* s_cnt  = (int*)otile0;            // 1024 ints scratch (pre-hotloop)
        int* s_wsum = s_cnt + NSPEC;           // 16
        for (int i = tid; i < NSPEC; i += THREADS) s_cnt[i] = 0;
        __syncthreads();
        for (int i = tid; i < NR1; i += THREADS) atomicAdd(&s_cnt[i1p[i]], 1);
        for (int i = tid; i < NR2; i += THREADS) atomicAdd(&s_cnt[i2p[i]], 1);
        __syncthreads();
        if (tid < 512) {                       // 16 warps scan 2 bins/thread
            const int a = s_cnt[2 * tid];
            const int b = s_cnt[2 * tid + 1];
            int incl = a + b;
#pragma unroll
            for (int d = 1; d < 32; d <<= 1) {
                int n = __shfl_up_sync(0xFFFFFFFFu, incl, d);
                if (lane >= d) incl += n;
            }
            if (lane == 31) s_wsum[warp] = incl;
            __syncthreads();
            if (warp == 0) {
                int w = (lane < 16) ? s_wsum[lane] : 0;
#pragma unroll
                for (int d = 1; d < 32; d <<= 1) {
                    int n = __shfl_up_sync(0xFFFFFFFFu, w, d);
                    if (lane >= d) w += n;
                }
                if (lane < 16) s_wsum[lane] = w;
            }
            __syncthreads();
            if (warp > 0) incl += s_wsum[warp - 1];
            const int e0 = incl - a - b;
            g_off[2 * tid]     = e0;
            g_off[2 * tid + 1] = e0 + a;
            if (tid == 511) g_off[NSPEC] = incl;
        } else {
            __syncthreads(); __syncthreads();
        }
        __threadfence();
        __syncthreads();
        if (tid == 0) atomicExch(&g_flag1, 1);
    }

    if (cta < NSETUP) {
        if (cta != 0) {
            if (tid == 0) {
                while (atomicAdd(&g_flag1, 0) == 0) __nanosleep(128);
            }
            __syncthreads();
        }
        const int per1 = NR1 / NSETUP, per2 = NR2 / NSETUP;
        for (int r = cta * per1 + tid; r < (cta + 1) * per1; r += THREADS) {
            const int p    = i1p[r];
            const int o0   = g_off[p], o1 = g_off[p + 1];
            const int cnt  = o1 - o0;
            const int posP = atomicAdd(&g_cur[p], 1) % cnt;   // epoch-free
            const int last = (posP == cnt - 1) ? 1 : 0;
            g_e[o0 + posP] = make_int4(i1r[r] * YPB, ONES_ROW * YPB,
                                       __float_as_int(k1[r]),
                                       ((p & 31) * YPB) | last);
        }
        for (int r = cta * per2 + tid; r < (cta + 1) * per2; r += THREADS) {
            const int p    = i2p[r];
            const int o0   = g_off[p], o1 = g_off[p + 1];
            const int cnt  = o1 - o0;
            const int posP = atomicAdd(&g_cur[p], 1) % cnt;
            const int last = (posP == cnt - 1) ? 1 : 0;
            g_e[o0 + posP] = make_int4(i2r[2 * r] * YPB, i2r[2 * r + 1] * YPB,
                                       __float_as_int(k2[r]),
                                       ((p & 31) * YPB) | last);
        }
        __threadfence();
        __syncthreads();
        if (tid == 0) atomicAdd(&g_ready, 1);
    }

    // ============ all CTAs: load y tile transposed into smem ================
    if (tid < NB) t_s[tid] = t_in[b0 + tid];
    if (tid < NB) y_s[ONES_ROW * YP + tid] = 1.0f;
    {
        const float4* y4 = (const float4*)(y_in + (size_t)b0 * NSPEC);
        for (int i = tid; i < NB * NSPEC / 4; i += THREADS) {
            const float4 v = y4[i];
            const int b = i >> 8;
            const int s = (i & 255) * 4;
            y_s[(s + 0) * YP + b] = v.x;
            y_s[(s + 1) * YP + b] = v.y;
            y_s[(s + 2) * YP + b] = v.z;
            y_s[(s + 3) * YP + b] = v.w;
        }
    }

    if (tid == 0) {
        while (atomicAdd(&g_ready, 0) < NSETUP) __nanosleep(128);
    }
    __syncthreads();

    // ============ hot loop: staged entries, full-block unrolled fast path ===
    const char* ysl  = (const char*)y_s + lane * 4;    // lane-baked base
    char*       otl  = otile0 + (warp * 32 * YP + lane) * 4;
    int4*       sbuf = sbuf_all + warp * 32;

    for (;;) {
        int c;
        if (lane == 0) c = atomicAdd(&s_chunk, 1);
        c = __shfl_sync(0xFFFFFFFFu, c, 0);
        if (c >= NCHUNK) break;
        const int pc = c * 32;
        const int j0 = g_off[pc];
        const int j1 = g_off[pc + 32];

#pragma unroll
        for (int pp = 0; pp < 32; ++pp)
            *(float*)(otl + pp * YPB) = 0.0f;

        float acc = 0.0f;

        // prefetch first block (coalesced: lane j -> entry j)
        int4 epf;
        if (j0 + lane < j1) epf = g_e[j0 + lane];

        for (int base = j0; base < j1; base += 32) {
            const int n = min(32, j1 - base);
            __syncwarp();
            if (lane < n) sbuf[lane] = epf;
            __syncwarp();
            const int nxt = base + 32;
            if (nxt + lane < j1) epf = g_e[nxt + lane];   // overlap next block

            if (n == 32) {
                // compile-time trip count: ptxas front-batches the LDS chain
#pragma unroll 8
                for (int t = 0; t < 16; ++t) PAIR_BODY(t)
            } else {
                const int npairs = n >> 1;
                for (int t = 0; t < npairs; ++t) PAIR_BODY(t)
                if (n & 1) {                   // odd tail of final block
                    const int4 e0 = sbuf[n - 1];
                    const float q0 = *(const float*)(ysl + e0.x) *
                                     *(const float*)(ysl + e0.y);
                    const float v0 = fmaf(__int_as_float(e0.z), q0, acc);
                    if (e0.w & 1) {
                        *(float*)(otl + (e0.w & ~3)) = v0;
                        acc = 0.0f;
                    } else {
                        acc = v0;
                    }
                }
            }
        }
        __syncwarp();   // otile visibility across lanes for transposed read

        const float* ot_rd = (const float*)(otile0 + (warp * 32 * YP + lane * YP) * 4);
#pragma unroll
        for (int row = 0; row < 32; ++row) {
            y_out[(size_t)(b0 + row) * NSPEC + pc + lane] = ot_rd[row] * t_s[row];
        }
        __syncwarp();
    }

    // ============ reset flags for next replay ===============================
    __syncthreads();
    if (tid == 0) {
        const int d = atomicAdd(&g_done, 1);
        if (d == grid_size - 1) {
            atomicExch(&g_ready, 0);
            atomicExch(&g_flag1, 0);
            atomicExch(&g_done, 0);
            // g_cur intentionally NOT reset (mod-cnt epoch trick)
        }
    }
}

// ---------------- launch -----------------------------------------------------
extern "C" void kernel_launch(void* const* d_in, const int* in_sizes, int n_in,
                              void* d_out, int out_size) {
    const float* t_in = (const float*)d_in[0];
    const float* y_in = (const float*)d_in[1];
    const float* k1   = (const float*)d_in[2];
    const float* k2   = (const float*)d_in[3];
    const int*   i1r  = (const int*)d_in[4];
    const int*   i1p  = (const int*)d_in[5];
    const int*   i2r  = (const int*)d_in[6];
    const int*   i2p  = (const int*)d_in[7];
    float* y_out = (float*)d_out;

    const int B    = in_sizes[0];
    const int grid = B / NB;   // 128

    cudaFuncSetAttribute(reaction_fused_kernel,
                         cudaFuncAttributeMaxDynamicSharedMemorySize, SMEM_BYTES);
    reaction_fused_kernel<<<grid, THREADS, SMEM_BYTES>>>(
        t_in, y_in, k1, k2, i1r, i1p, i2r, i2p, y_out, grid);
}